// round 17
// baseline (speedup 1.0000x reference)
#include <cuda_runtime.h>
#include <math.h>
#include <stdint.h>

// Shape fixed by reference: [4,1,128,256,256] fp32
#define IMG_W    256
#define IMG_H    256
#define NSLICES  512                   // B*D
#define STRIP_H  32                    // output rows per block
#define STRIPS   (IMG_H / STRIP_H)     // 8
#define NB       (NSLICES * STRIPS)    // 4096 blocks
#define TROWS    (STRIP_H + 2)         // 34 tile rows (with halo)
#define PADF     4                     // left zero-pad floats per smem row
#define ROWF     264                   // smem row stride in floats (16B mult)
#define IMGF     (TROWS * ROWF)        // floats per image tile
#define SMEM_BYTES (2 * IMGF * 4)      // 71808 B
#define HR       4                     // output rows per thread per half
#define N_TOTAL  (4.0 * 128.0 * 256.0 * 256.0)

__device__ float        g_partials[NB];
__device__ unsigned int g_count = 0;

__device__ __forceinline__ float sqrt_approx(float x) {
    float r; asm("sqrt.approx.f32 %0, %1;" : "=f"(r) : "f"(x)); return r;
}

// Row aggregates for 4 columns straight from padded smem (no guards, no SELs):
//   h1 = r - l        (ex = h1[y-1] + 2h1[y] + h1[y+1])
//   h2 = l + 2m + r   (ey = h2[y+1] - h2[y-1])
__device__ __forceinline__ void agg_sm(const float* __restrict__ p,
                                       float h1[4], float h2[4])
{
    const float4 v = *reinterpret_cast<const float4*>(p);   // LDS.128
    const float  l = p[-1];                                 // LDS.32 (pad=0 at edge)
    const float  r = p[4];                                  // LDS.32
    h1[0] = v.y - l;    h2[0] = fmaf(2.f, v.x, l + v.y);
    h1[1] = v.z - v.x;  h2[1] = fmaf(2.f, v.y, v.x + v.z);
    h1[2] = v.w - v.y;  h2[2] = fmaf(2.f, v.z, v.y + v.w);
    h1[3] = r - v.z;    h2[3] = fmaf(2.f, v.w, v.z + r);
}

// Compute HR output rows starting at tile row (lr0 + HR*g + 1).
// P0/T0 point at the thread's first prologue row (tile row lr0 + HR*g).
__device__ __forceinline__ float compute_half(const float* __restrict__ P0,
                                              const float* __restrict__ T0)
{
    float pp1[4], pp2[4], pc1[4], pc2[4];
    float tp1[4], tp2[4], tc1[4], tc2[4];
    agg_sm(P0,        pp1, pp2);
    agg_sm(P0 + ROWF, pc1, pc2);
    agg_sm(T0,        tp1, tp2);
    agg_sm(T0 + ROWF, tc1, tc2);

    float acc = 0.f;
    #pragma unroll
    for (int i = 0; i < HR; i++) {
        float pn1[4], pn2[4], tn1[4], tn2[4];
        agg_sm(P0 + (i + 2) * ROWF, pn1, pn2);
        agg_sm(T0 + (i + 2) * ROWF, tn1, tn2);

        #pragma unroll
        for (int j = 0; j < 4; j++) {
            float ex = fmaf(2.f, pc1[j], pp1[j]) + pn1[j];
            float ey = pn2[j] - pp2[j];
            const float magp = sqrt_approx(fmaf(ex, ex, fmaf(ey, ey, 1e-8f)));

            ex = fmaf(2.f, tc1[j], tp1[j]) + tn1[j];
            ey = tn2[j] - tp2[j];
            const float magt = sqrt_approx(fmaf(ex, ex, fmaf(ey, ey, 1e-8f)));

            acc += fabsf(magp - magt);
        }

        #pragma unroll
        for (int j = 0; j < 4; j++) {
            pp1[j] = pc1[j]; pc1[j] = pn1[j];
            pp2[j] = pc2[j]; pc2[j] = pn2[j];
            tp1[j] = tc1[j]; tc1[j] = tn1[j];
            tp2[j] = tc2[j]; tc2[j] = tn2[j];
        }
    }
    return acc;
}

__global__ __launch_bounds__(256)
void edge_loss_kernel(const float* __restrict__ pred,
                      const float* __restrict__ target,
                      float* __restrict__ out)
{
    extern __shared__ float sm[];          // [2][TROWS][ROWF]
    __shared__ float warp_sums[8];
    __shared__ int   s_last;

    const int tid  = threadIdx.x;
    const int lane = tid & 31;
    const int r0   = blockIdx.x * STRIP_H;
    const size_t base = (size_t)blockIdx.y * (IMG_H * IMG_W);

    // ---- Zero the left/right column pads (once) ----
    for (int idx = tid; idx < 2 * TROWS * 2; idx += 256) {   // 136 chunks
        const int img  = idx & 1;
        const int rem  = idx >> 1;          // 0..67
        const int row  = rem >> 1;          // 0..33
        const int side = rem & 1;
        float* dst = sm + img * IMGF + row * ROWF + (side ? (PADF + IMG_W) : 0);
        *reinterpret_cast<float4*>(dst) = make_float4(0.f, 0.f, 0.f, 0.f);
    }

    // ---- Double-buffered bulk fill ----
    // k covers tile rows 2k..2k+1 (both images via thread parity).
    // Group A: k=0..8 (rows 0..17).  Group B: k=9..16 (rows 18..33).
    const float* __restrict__ gimg = ((tid & 1) ? target : pred) + base;
    const int h0   = tid >> 1;              // 0..127
    const int imgo = (tid & 1) * IMGF;

    #pragma unroll
    for (int k = 0; k < 9; k++) {
        const int half = k * 128 + h0;
        const int row  = half >> 6;
        const int c16  = half & 63;
        float* dst = sm + imgo + row * ROWF + PADF + c16 * 4;
        const uint32_t sa = (uint32_t)__cvta_generic_to_shared(dst);
        const int gr = r0 - 1 + row;
        if (gr >= 0 && gr < IMG_H) {
            const float* g = gimg + (size_t)gr * IMG_W + c16 * 4;
            asm volatile("cp.async.cg.shared.global [%0], [%1], 16;"
                         :: "r"(sa), "l"(g));
        } else {
            asm volatile("st.shared.v4.b32 [%0], {%1,%1,%1,%1};"
                         :: "r"(sa), "r"(0u));
        }
    }
    asm volatile("cp.async.commit_group;");     // group A

    #pragma unroll
    for (int k = 9; k < 17; k++) {
        const int half = k * 128 + h0;
        const int row  = half >> 6;
        const int c16  = half & 63;
        float* dst = sm + imgo + row * ROWF + PADF + c16 * 4;
        const uint32_t sa = (uint32_t)__cvta_generic_to_shared(dst);
        const int gr = r0 - 1 + row;
        if (gr < IMG_H) {                       // row >= 18 here, gr >= 17 >= 0
            const float* g = gimg + (size_t)gr * IMG_W + c16 * 4;
            asm volatile("cp.async.cg.shared.global [%0], [%1], 16;"
                         :: "r"(sa), "l"(g));
        } else {
            asm volatile("st.shared.v4.b32 [%0], {%1,%1,%1,%1};"
                         :: "r"(sa), "r"(0u));
        }
    }
    asm volatile("cp.async.commit_group;");     // group B

    // ---- Half A: rows landed; B still streaming from DRAM ----
    asm volatile("cp.async.wait_group 1;");
    __syncthreads();

    const int x  = tid & 63;                // col group -> cols [4x, 4x+3]
    const int g  = tid >> 6;                // y group
    const int cb = x << 2;

    // First half: outputs local rows 0..15 (tile rows 0..17 = A only)
    const float* PA = sm + (g * HR) * ROWF + PADF + cb;
    float acc = compute_half(PA, PA + IMGF);

    // ---- Half B landed ----
    asm volatile("cp.async.wait_group 0;");
    __syncthreads();

    // Second half: outputs local rows 16..31 (tile rows 16..33)
    const float* PB = sm + (16 + g * HR) * ROWF + PADF + cb;
    acc += compute_half(PB, PB + IMGF);

    // ---- Deterministic block reduction ----
    #pragma unroll
    for (int offr = 16; offr > 0; offr >>= 1)
        acc += __shfl_down_sync(0xffffffffu, acc, offr);
    if (lane == 0) warp_sums[tid >> 5] = acc;
    __syncthreads();

    if (tid == 0) {
        float s = 0.f;
        #pragma unroll
        for (int i = 0; i < 8; i++) s += warp_sums[i];
        g_partials[blockIdx.y * gridDim.x + blockIdx.x] = s;
        __threadfence();
        const unsigned old = atomicAdd(&g_count, 1u);
        s_last = (old == NB - 1) ? 1 : 0;
    }
    __syncthreads();

    // ---- Last block: deterministic final reduce (fixed order, double) ----
    if (s_last) {
        __shared__ double dred[256];
        double s = 0.0;
        #pragma unroll 8
        for (int i = tid; i < NB; i += 256)
            s += (double)g_partials[i];
        dred[tid] = s;
        __syncthreads();
        #pragma unroll
        for (int offr = 128; offr > 0; offr >>= 1) {
            if (tid < offr) dred[tid] += dred[tid + offr];
            __syncthreads();
        }
        if (tid == 0) {
            out[0]  = (float)(dred[0] / N_TOTAL);
            g_count = 0;   // reset for next graph replay
        }
    }
}

extern "C" void kernel_launch(void* const* d_in, const int* in_sizes, int n_in,
                              void* d_out, int out_size)
{
    (void)in_sizes; (void)n_in; (void)out_size;
    const float* pred   = (const float*)d_in[0];
    const float* target = (const float*)d_in[1];
    float* out = (float*)d_out;

    cudaFuncSetAttribute(edge_loss_kernel,
                         cudaFuncAttributeMaxDynamicSharedMemorySize, SMEM_BYTES);

    dim3 grid(STRIPS, NSLICES);   // 8 x 512 = 4096 blocks
    edge_loss_kernel<<<grid, 256, SMEM_BYTES>>>(pred, target, out);
}